// round 16
// baseline (speedup 1.0000x reference)
#include <cuda_runtime.h>
#include <cstdint>
#include <cstddef>

#define N_NODES 100000
#define N_EDGES 1600000
#define F_IN    64
#define HIDDEN  128
#define N_GRAPHS 1024
#define EPS 1e-5f

#define SCAN_BLK 256
#define N_SCAN_BLOCKS ((N_NODES + SCAN_BLK - 1) / SCAN_BLK)   // 391
#define N_TILES64 ((N_NODES + 63) / 64)                        // 1563
#define N_TILES128 ((N_NODES + 127) / 128)                     // 782

// ---------------- static scratch (no allocation allowed) ----------------
__device__ float g_hr[(size_t)N_NODES * HIDDEN];
__device__ float g_ho[(size_t)N_NODES * HIDDEN];    // also agg0
__device__ float g_ha[(size_t)N_NODES * HIDDEN];    // final activations
__device__ float g_hb[(size_t)N_NODES * HIDDEN];    // layer-1 output (row-major)

// A-fragment image for layer-1 GEMM (split bf16, quad-major, 8192 words/tile)
// +1 guard tile (zero, never written) so 128-row GEMM blocks stay in-bounds.
__device__ __align__(16) uint32_t g_af1[(size_t)(2 * N_TILES128) * 8192];

__device__ float g_scale[3][HIDDEN];
__device__ float g_shift[3][HIDDEN];

// B fragments (split bf16, quad-major):
// layer0 (fused, N=128,K'=128): 16384 words @0 ; layers1/2 (N=256,K=128): 32768 @16384/49152
__device__ __align__(16) uint32_t g_Bf[16384 + 32768 + 32768];

__device__ int   g_deg[N_NODES];
__device__ int   g_epos[N_EDGES];
__device__ int   g_incl[N_SCAN_BLOCKS * SCAN_BLK];
__device__ int   g_bsum[N_SCAN_BLOCKS];
__device__ int   g_boff[N_SCAN_BLOCKS];
__device__ __align__(8) int2 g_csr[N_EDGES];        // (src, ew-bits)

__device__ __forceinline__ uint32_t bf16x2(float x0, float x1) {
    uint32_t r;
    asm("cvt.rn.bf16x2.f32 %0, %1, %2;" : "=r"(r) : "f"(x1), "f"(x0));
    return r;
}
__device__ __forceinline__ void split2(float a, float b, uint32_t& hi, uint32_t& lo) {
    hi = bf16x2(a, b);
    float h0 = __uint_as_float(hi << 16);
    float h1 = __uint_as_float(hi & 0xffff0000u);
    lo = bf16x2(a - h0, b - h1);
}

__device__ __forceinline__ void mma16(float* c, uint4 a, uint32_t b0, uint32_t b1) {
    asm volatile(
        "mma.sync.aligned.m16n8k16.row.col.f32.bf16.bf16.f32 "
        "{%0,%1,%2,%3}, {%4,%5,%6,%7}, {%8,%9}, {%0,%1,%2,%3};"
        : "+f"(c[0]), "+f"(c[1]), "+f"(c[2]), "+f"(c[3])
        : "r"(a.x), "r"(a.y), "r"(a.z), "r"(a.w), "r"(b0), "r"(b1));
}
__device__ __forceinline__ void mma_row(float (*accRow)[4], uint4 a,
                                        uint4 b0, uint4 b1, uint4 b2, uint4 b3) {
    mma16(accRow[0], a, b0.x, b0.y);  mma16(accRow[1], a, b0.z, b0.w);
    mma16(accRow[2], a, b1.x, b1.y);  mma16(accRow[3], a, b1.z, b1.w);
    mma16(accRow[4], a, b2.x, b2.y);  mma16(accRow[5], a, b2.z, b2.w);
    mma16(accRow[6], a, b3.x, b3.y);  mma16(accRow[7], a, b3.z, b3.w);
}

// ======================= CSR build (by dst) ==============================
__global__ void hist_kernel(const int* __restrict__ dst,
                            int* __restrict__ deg,
                            int* __restrict__ epos)
{
    int e = blockIdx.x * blockDim.x + threadIdx.x;
    if (e < N_EDGES) epos[e] = atomicAdd(deg + __ldg(dst + e), 1);
}

__global__ void scan1_kernel(const int* __restrict__ deg,
                             int* __restrict__ incl, int* __restrict__ bsum)
{
    __shared__ int s[SCAN_BLK];
    int gid = blockIdx.x * SCAN_BLK + threadIdx.x;
    int v = (gid < N_NODES) ? deg[gid] : 0;
    s[threadIdx.x] = v;
    __syncthreads();
    #pragma unroll
    for (int off = 1; off < SCAN_BLK; off <<= 1) {
        int t = (threadIdx.x >= off) ? s[threadIdx.x - off] : 0;
        __syncthreads();
        s[threadIdx.x] += t;
        __syncthreads();
    }
    incl[gid] = s[threadIdx.x];
    if (threadIdx.x == SCAN_BLK - 1) bsum[blockIdx.x] = s[threadIdx.x];
}

__global__ void scan2_kernel(const int* __restrict__ bsum, int* __restrict__ boff)
{
    __shared__ int s[512];
    int t = threadIdx.x;
    s[t] = (t < N_SCAN_BLOCKS) ? bsum[t] : 0;
    __syncthreads();
    #pragma unroll
    for (int off = 1; off < 512; off <<= 1) {
        int v = (t >= off) ? s[t - off] : 0;
        __syncthreads();
        s[t] += v;
        __syncthreads();
    }
    if (t < N_SCAN_BLOCKS) boff[t] = s[t] - bsum[t];
}

__global__ void fill_kernel(const int* __restrict__ src,
                            const int* __restrict__ dst,
                            const float* __restrict__ ew,
                            const int* __restrict__ deg,
                            const int* __restrict__ incl,
                            const int* __restrict__ boff,
                            const int* __restrict__ epos,
                            int2* __restrict__ csr)
{
    int e = blockIdx.x * blockDim.x + threadIdx.x;
    if (e >= N_EDGES) return;
    int d = __ldg(dst + e);
    int base = __ldg(incl + d) - __ldg(deg + d) + __ldg(boff + (d >> 8));
    csr[base + __ldg(epos + e)] =
        make_int2(__ldg(src + e), __float_as_int(__ldg(ew + e)));
}

// ======= merged prep: layer0 B + layers1/2 B + BN fold (one launch) ======
__global__ void prep_all_kernel(const float* __restrict__ Wr0, const float* __restrict__ Wo0,
                                const float* __restrict__ Wr1, const float* __restrict__ Wo1,
                                const float* __restrict__ Wr2, const float* __restrict__ Wo2,
                                const float* __restrict__ br0, const float* __restrict__ g0,
                                const float* __restrict__ b0,  const float* __restrict__ m0,
                                const float* __restrict__ v0,
                                const float* __restrict__ br1, const float* __restrict__ g1,
                                const float* __restrict__ b1,  const float* __restrict__ m1,
                                const float* __restrict__ v1,
                                const float* __restrict__ br2, const float* __restrict__ g2,
                                const float* __restrict__ b2,  const float* __restrict__ m2,
                                const float* __restrict__ v2)
{
    int blk = blockIdx.x;
    if (blk < 64) {
        int rem = blk * 256 + threadIdx.x;
        int w    = rem & 3;
        int lane = (rem >> 2) & 31;
        int q    = (rem >> 7) & 3;
        int ng   = (rem >> 9) & 1;
        int t    = rem >> 10;
        int ks   = t & 7;
        int hilo = t >> 3;
        int idx  = q * 4 + w;
        int nt = idx >> 1, breg = idx & 1;
        int k0 = ks * 16 + (lane & 3) * 2 + breg * 8;
        int n  = ng * 64 + nt * 8 + (lane >> 2);
        float w0, w1;
        if (k0 < 64) { w0 = __ldg(Wr0 + k0 * 128 + n); w1 = __ldg(Wr0 + (k0 + 1) * 128 + n); }
        else         { w0 = __ldg(Wo0 + (k0 - 64) * 128 + n); w1 = __ldg(Wo0 + (k0 - 63) * 128 + n); }
        uint32_t hi, lo;
        split2(w0, w1, hi, lo);
        g_Bf[rem] = hilo ? lo : hi;
    } else if (blk < 320) {
        int id = (blk - 64) * 256 + threadIdx.x;
        int base, rem;
        const float *Wr, *Wo;
        if (id < 32768) { base = 16384; rem = id;          Wr = Wr1; Wo = Wo1; }
        else            { base = 49152; rem = id - 32768;  Wr = Wr2; Wo = Wo2; }
        int w    = rem & 3;
        int lane = (rem >> 2) & 31;
        int q    = (rem >> 7) & 3;
        int ng   = (rem >> 9) & 3;
        int t    = rem >> 11;
        int ks   = t & 7;
        int hilo = t >> 3;
        int idx  = q * 4 + w;
        int nt = idx >> 1, breg = idx & 1;
        int k0 = ks * 16 + (lane & 3) * 2 + breg * 8;
        int n  = ng * 64 + nt * 8 + (lane >> 2);
        int jj = n & 127;
        const float* W = (n < 128) ? Wr : Wo;
        float w0 = __ldg(W + (k0 + 0) * 128 + jj);
        float w1 = __ldg(W + (k0 + 1) * 128 + jj);
        uint32_t hi, lo;
        split2(w0, w1, hi, lo);
        g_Bf[base + rem] = hilo ? lo : hi;
    } else {
        int j = threadIdx.x;
        if (j < 128) {
            for (int l = 0; l < 3; l++) {
                const float* br = (l == 0) ? br0 : (l == 1) ? br1 : br2;
                const float* g  = (l == 0) ? g0  : (l == 1) ? g1  : g2;
                const float* b  = (l == 0) ? b0  : (l == 1) ? b1  : b2;
                const float* m  = (l == 0) ? m0  : (l == 1) ? m1  : m2;
                const float* v  = (l == 0) ? v0  : (l == 1) ? v1  : v2;
                float s = g[j] * rsqrtf(v[j] + EPS);
                g_scale[l][j] = s;
                g_shift[l][j] = (br[j] - m[j]) * s + b[j];
            }
        }
    }
}

// ============== layer-0 gather: agg[n] = Σ ew*x[src] (D=64) ==============
__global__ void gather64_kernel(const float* __restrict__ x,
                                const int* __restrict__ deg,
                                const int* __restrict__ incl,
                                const int* __restrict__ boff,
                                const int2* __restrict__ csr,
                                float* __restrict__ agg)
{
    int node = (blockIdx.x * blockDim.x + threadIdx.x) >> 5;
    if (node >= N_NODES) return;
    int lane = threadIdx.x & 31;
    int end = __ldg(incl + node) + __ldg(boff + (node >> 8));
    int beg = end - __ldg(deg + node);

    const float2* x2 = reinterpret_cast<const float2*>(x);
    float2 acc = make_float2(0.f, 0.f);
    int i = beg;
    for (; i + 1 < end; i += 2) {
        int2 p0 = __ldg(csr + i);
        int2 p1 = __ldg(csr + i + 1);
        float e0 = __int_as_float(p0.y);
        float e1 = __int_as_float(p1.y);
        float2 v0 = x2[(size_t)p0.x * 32 + lane];
        float2 v1 = x2[(size_t)p1.x * 32 + lane];
        acc.x = fmaf(v0.x, e0, acc.x); acc.y = fmaf(v0.y, e0, acc.y);
        acc.x = fmaf(v1.x, e1, acc.x); acc.y = fmaf(v1.y, e1, acc.y);
    }
    if (i < end) {
        int2 p0 = __ldg(csr + i);
        float e0 = __int_as_float(p0.y);
        float2 v0 = x2[(size_t)p0.x * 32 + lane];
        acc.x = fmaf(v0.x, e0, acc.x); acc.y = fmaf(v0.y, e0, acc.y);
    }
    reinterpret_cast<float2*>(agg + (size_t)node * 64)[lane] = acc;
}

// ====== layer-0 fused GEMM (direct A loads, no smem) -> af1 fragments ====
__global__ void __launch_bounds__(128, 4)
gemm_fused_kernel(const float* __restrict__ agg, const float* __restrict__ h,
                  const uint32_t* __restrict__ Bf,
                  const float* __restrict__ scale, const float* __restrict__ shift,
                  uint32_t* __restrict__ AFrag)
{
    const int w    = threadIdx.x >> 5;
    const int lane = threadIdx.x & 31;
    const int mg   = w >> 1;
    const int ng   = w & 1;
    const int n0   = blockIdx.x * 64;

    float acc[2][8][4];
    #pragma unroll
    for (int mt = 0; mt < 2; mt++)
        #pragma unroll
        for (int nt = 0; nt < 8; nt++)
            #pragma unroll
            for (int r = 0; r < 4; r++) acc[mt][nt][r] = 0.f;

    const uint4* BfQ = reinterpret_cast<const uint4*>(Bf);
    const int rbase = n0 + mg * 32 + (lane >> 2);
    const int kcol  = (lane & 3) * 2;

    for (int gks = 0; gks < 8; gks++) {
        const float* srcP = (gks < 4) ? agg : h;
        const int kb = (gks & 3) * 16;

        uint4 ah[2], al[2];
        #pragma unroll
        for (int mt = 0; mt < 2; mt++) {
            uint32_t hw[4], lw[4];
            #pragma unroll
            for (int r = 0; r < 4; r++) {
                int row = rbase + mt * 16 + (r & 1) * 8;
                int k0  = kb + kcol + ((r >> 1) & 1) * 8;
                float2 v = make_float2(0.f, 0.f);
                if (row < N_NODES)
                    v = *reinterpret_cast<const float2*>(srcP + (size_t)row * 64 + k0);
                split2(v.x, v.y, hw[r], lw[r]);
            }
            ah[mt] = make_uint4(hw[0], hw[1], hw[2], hw[3]);
            al[mt] = make_uint4(lw[0], lw[1], lw[2], lw[3]);
        }

        const uint4* bHi = BfQ + (((0 * 8 + gks) * 2 + ng) * 4) * 32 + lane;
        uint4 bh0 = __ldg(bHi + 0 * 32);
        uint4 bh1 = __ldg(bHi + 1 * 32);
        uint4 bh2 = __ldg(bHi + 2 * 32);
        uint4 bh3 = __ldg(bHi + 3 * 32);

        mma_row(acc[0], ah[0], bh0, bh1, bh2, bh3);
        mma_row(acc[1], ah[1], bh0, bh1, bh2, bh3);
        mma_row(acc[0], al[0], bh0, bh1, bh2, bh3);
        mma_row(acc[1], al[1], bh0, bh1, bh2, bh3);

        const uint4* bLo = BfQ + (((1 * 8 + gks) * 2 + ng) * 4) * 32 + lane;
        uint4 bl0 = __ldg(bLo + 0 * 32);
        uint4 bl1 = __ldg(bLo + 1 * 32);
        uint4 bl2 = __ldg(bLo + 2 * 32);
        uint4 bl3 = __ldg(bLo + 3 * 32);

        mma_row(acc[0], ah[0], bl0, bl1, bl2, bl3);
        mma_row(acc[1], ah[1], bl0, bl1, bl2, bl3);
    }

    // ---- epilogue: BN + bias + ReLU, emit A-fragments for layer 1 ----
    uint32_t* AF = AFrag + (size_t)blockIdx.x * 8192;
    #pragma unroll
    for (int mt = 0; mt < 2; mt++) {
        #pragma unroll
        for (int q = 0; q < 4; q++) {
            int ks = ng * 4 + q;
            int c0 = ng * 64 + 2 * q * 8 + 2 * (lane & 3);
            float2 sc0 = *reinterpret_cast<const float2*>(scale + c0);
            float2 sh0 = *reinterpret_cast<const float2*>(shift + c0);
            float2 sc1 = *reinterpret_cast<const float2*>(scale + c0 + 8);
            float2 sh1 = *reinterpret_cast<const float2*>(shift + c0 + 8);
            float v00 = fmaxf(fmaf(acc[mt][2*q][0],   sc0.x, sh0.x), 0.f);
            float v01 = fmaxf(fmaf(acc[mt][2*q][1],   sc0.y, sh0.y), 0.f);
            float v10 = fmaxf(fmaf(acc[mt][2*q][2],   sc0.x, sh0.x), 0.f);
            float v11 = fmaxf(fmaf(acc[mt][2*q][3],   sc0.y, sh0.y), 0.f);
            float w00 = fmaxf(fmaf(acc[mt][2*q+1][0], sc1.x, sh1.x), 0.f);
            float w01 = fmaxf(fmaf(acc[mt][2*q+1][1], sc1.y, sh1.y), 0.f);
            float w10 = fmaxf(fmaf(acc[mt][2*q+1][2], sc1.x, sh1.x), 0.f);
            float w11 = fmaxf(fmaf(acc[mt][2*q+1][3], sc1.y, sh1.y), 0.f);
            uint4 hi, lo;
            split2(v00, v01, hi.x, lo.x);
            split2(v10, v11, hi.y, lo.y);
            split2(w00, w01, hi.z, lo.z);
            split2(w10, w11, hi.w, lo.w);
            int qb = (mg * 8 + ks) * 4;
            *reinterpret_cast<uint4*>(&AF[((qb + mt * 2 + 0) * 32 + lane) * 4]) = hi;
            *reinterpret_cast<uint4*>(&AF[((qb + mt * 2 + 1) * 32 + lane) * 4]) = lo;
        }
    }
}

// ====== layer-1 GEMM, M=128 tile (512 thr, no smem): A-fragments =========
__global__ void __launch_bounds__(512, 1)
gemm_frag_kernel(const uint32_t* __restrict__ AFrag,
                 const uint32_t* __restrict__ Bf,
                 float* __restrict__ hr,
                 float* __restrict__ ho)
{
    const int w    = threadIdx.x >> 5;     // 0..15
    const int lane = threadIdx.x & 31;
    const int mg   = w >> 2;               // 0..3
    const int ng   = w & 3;                // 0..3
    const int n0   = blockIdx.x * 128;

    float acc[2][8][4];
    #pragma unroll
    for (int mt = 0; mt < 2; mt++)
        #pragma unroll
        for (int nt = 0; nt < 8; nt++)
            #pragma unroll
            for (int r = 0; r < 4; r++) acc[mt][nt][r] = 0.f;

    // af1 tile for this warp: 64-row tiles, 2 per block
    const uint4* AQ  = reinterpret_cast<const uint4*>(AFrag) +
                       ((size_t)blockIdx.x * 2 + (mg >> 1)) * 2048;
    const int mgl = mg & 1;
    const uint4* BfQ = reinterpret_cast<const uint4*>(Bf);

    for (int ks = 0; ks < 8; ks++) {
        const uint4* aB = AQ + ((mgl * 8 + ks) * 4) * 32 + lane;
        uint4 a0h = __ldg(aB + 0 * 32);
        uint4 a0l = __ldg(aB + 1 * 32);
        uint4 a1h = __ldg(aB + 2 * 32);
        uint4 a1l = __ldg(aB + 3 * 32);

        const uint4* bHi = BfQ + (((0 * 8 + ks) * 4 + ng) * 4) * 32 + lane;
        uint4 bh0 = __ldg(bHi + 0 * 32);
        uint4 bh1 = __ldg(bHi + 1 * 32);
        uint4 bh2 = __ldg(bHi + 2 * 32);
        uint4 bh3 = __ldg(bHi + 3 * 32);

        mma_row(acc[0], a0h, bh0, bh1, bh2, bh3);
        mma_row(acc[1], a1h, bh0, bh1, bh2, bh3);
        mma_row(acc[0], a0l, bh0, bh1, bh2, bh3);
        mma_row(acc[1], a1l, bh0, bh1, bh2, bh3);

        const uint4* bLo = BfQ + (((1 * 8 + ks) * 4 + ng) * 4) * 32 + lane;
        uint4 bl0 = __ldg(bLo + 0 * 32);
        uint4 bl1 = __ldg(bLo + 1 * 32);
        uint4 bl2 = __ldg(bLo + 2 * 32);
        uint4 bl3 = __ldg(bLo + 3 * 32);

        mma_row(acc[0], a0h, bl0, bl1, bl2, bl3);
        mma_row(acc[1], a1h, bl0, bl1, bl2, bl3);
    }

    float* dst = (ng < 2) ? hr : ho;
    const int colbase = (ng & 1) * 64;
    #pragma unroll
    for (int mt = 0; mt < 2; mt++) {
        int row = n0 + mg * 32 + mt * 16 + (lane >> 2);
        #pragma unroll
        for (int nt = 0; nt < 8; nt++) {
            int col = colbase + nt * 8 + 2 * (lane & 3);
            if (row < N_NODES)
                *reinterpret_cast<float2*>(dst + (size_t)row * 128 + col) =
                    make_float2(acc[mt][nt][0], acc[mt][nt][1]);
            if (row + 8 < N_NODES)
                *reinterpret_cast<float2*>(dst + (size_t)(row + 8) * 128 + col) =
                    make_float2(acc[mt][nt][2], acc[mt][nt][3]);
        }
    }
}

// ====== layer-2 GEMM, M=128 tile (512 thr, no smem): direct A loads ======
__global__ void __launch_bounds__(512, 1)
gemm_direct_kernel(const float* __restrict__ h,
                   const uint32_t* __restrict__ Bf,
                   float* __restrict__ hr,
                   float* __restrict__ ho)
{
    const int w    = threadIdx.x >> 5;     // 0..15
    const int lane = threadIdx.x & 31;
    const int mg   = w >> 2;               // 0..3
    const int ng   = w & 3;                // 0..3
    const int n0   = blockIdx.x * 128;

    float acc[2][8][4];
    #pragma unroll
    for (int mt = 0; mt < 2; mt++)
        #pragma unroll
        for (int nt = 0; nt < 8; nt++)
            #pragma unroll
            for (int r = 0; r < 4; r++) acc[mt][nt][r] = 0.f;

    const uint4* BfQ = reinterpret_cast<const uint4*>(Bf);
    const int rbase = n0 + mg * 32 + (lane >> 2);
    const int kcol  = (lane & 3) * 2;

    for (int ks = 0; ks < 8; ks++) {
        uint4 ah[2], al[2];
        #pragma unroll
        for (int mt = 0; mt < 2; mt++) {
            uint32_t hw[4], lw[4];
            #pragma unroll
            for (int r = 0; r < 4; r++) {
                int row = rbase + mt * 16 + (r & 1) * 8;
                int k0  = ks * 16 + kcol + ((r >> 1) & 1) * 8;
                float2 v = make_float2(0.f, 0.f);
                if (row < N_NODES)
                    v = *reinterpret_cast<const float2*>(h + (size_t)row * 128 + k0);
                split2(v.x, v.y, hw[r], lw[r]);
            }
            ah[mt] = make_uint4(hw[0], hw[1], hw[2], hw[3]);
            al[mt] = make_uint4(lw[0], lw[1], lw[2], lw[3]);
        }

        const uint4* bHi = BfQ + (((0 * 8 + ks) * 4 + ng) * 4) * 32 + lane;
        uint4 bh0 = __ldg(bHi + 0 * 32);
        uint4 bh1 = __ldg(bHi + 1 * 32);
        uint4 bh2 = __ldg(bHi + 2 * 32);
        uint4 bh3 = __ldg(bHi + 3 * 32);

        mma_row(acc[0], ah[0], bh0, bh1, bh2, bh3);
        mma_row(acc[1], ah[1], bh0, bh1, bh2, bh3);
        mma_row(acc[0], al[0], bh0, bh1, bh2, bh3);
        mma_row(acc[1], al[1], bh0, bh1, bh2, bh3);

        const uint4* bLo = BfQ + (((1 * 8 + ks) * 4 + ng) * 4) * 32 + lane;
        uint4 bl0 = __ldg(bLo + 0 * 32);
        uint4 bl1 = __ldg(bLo + 1 * 32);
        uint4 bl2 = __ldg(bLo + 2 * 32);
        uint4 bl3 = __ldg(bLo + 3 * 32);

        mma_row(acc[0], ah[0], bl0, bl1, bl2, bl3);
        mma_row(acc[1], ah[1], bl0, bl1, bl2, bl3);
    }

    float* dst = (ng < 2) ? hr : ho;
    const int colbase = (ng & 1) * 64;
    #pragma unroll
    for (int mt = 0; mt < 2; mt++) {
        int row = n0 + mg * 32 + mt * 16 + (lane >> 2);
        #pragma unroll
        for (int nt = 0; nt < 8; nt++) {
            int col = colbase + nt * 8 + 2 * (lane & 3);
            if (row < N_NODES)
                *reinterpret_cast<float2*>(dst + (size_t)row * 128 + col) =
                    make_float2(acc[mt][nt][0], acc[mt][nt][1]);
            if (row + 8 < N_NODES)
                *reinterpret_cast<float2*>(dst + (size_t)(row + 8) * 128 + col) =
                    make_float2(acc[mt][nt][2], acc[mt][nt][3]);
        }
    }
}

// === fused gather + root + BN + ReLU (warp-per-node, row-major out) ======
__global__ void gather_fused_kernel(const float* __restrict__ hr,
                                    const float* __restrict__ ho,
                                    const int* __restrict__ deg,
                                    const int* __restrict__ incl,
                                    const int* __restrict__ boff,
                                    const int2* __restrict__ csr,
                                    const float* __restrict__ scale,
                                    const float* __restrict__ shift,
                                    float* __restrict__ out)
{
    int node = (blockIdx.x * blockDim.x + threadIdx.x) >> 5;
    if (node >= N_NODES) return;
    int lane = threadIdx.x & 31;
    int end = __ldg(incl + node) + __ldg(boff + (node >> 8));
    int beg = end - __ldg(deg + node);

    const float4* hr4 = reinterpret_cast<const float4*>(hr);
    float4 acc = *(reinterpret_cast<const float4*>(ho + (size_t)node * 128) + lane);

    int i = beg;
    for (; i + 3 < end; i += 4) {
        int2 p0 = __ldg(csr + i);
        int2 p1 = __ldg(csr + i + 1);
        int2 p2 = __ldg(csr + i + 2);
        int2 p3 = __ldg(csr + i + 3);
        float4 v0 = hr4[(size_t)p0.x * 32 + lane];
        float4 v1 = hr4[(size_t)p1.x * 32 + lane];
        float4 v2 = hr4[(size_t)p2.x * 32 + lane];
        float4 v3 = hr4[(size_t)p3.x * 32 + lane];
        float e0 = __int_as_float(p0.y), e1 = __int_as_float(p1.y);
        float e2 = __int_as_float(p2.y), e3 = __int_as_float(p3.y);
        acc.x = fmaf(v0.x, e0, acc.x); acc.y = fmaf(v0.y, e0, acc.y);
        acc.z = fmaf(v0.z, e0, acc.z); acc.w = fmaf(v0.w, e0, acc.w);
        acc.x = fmaf(v1.x, e1, acc.x); acc.y = fmaf(v1.y, e1, acc.y);
        acc.z = fmaf(v1.z, e1, acc.z); acc.w = fmaf(v1.w, e1, acc.w);
        acc.x = fmaf(v2.x, e2, acc.x); acc.y = fmaf(v2.y, e2, acc.y);
        acc.z = fmaf(v2.z, e2, acc.z); acc.w = fmaf(v2.w, e2, acc.w);
        acc.x = fmaf(v3.x, e3, acc.x); acc.y = fmaf(v3.y, e3, acc.y);
        acc.z = fmaf(v3.z, e3, acc.z); acc.w = fmaf(v3.w, e3, acc.w);
    }
    for (; i < end; i++) {
        int2 p0 = __ldg(csr + i);
        float e0 = __int_as_float(p0.y);
        float4 v0 = hr4[(size_t)p0.x * 32 + lane];
        acc.x = fmaf(v0.x, e0, acc.x); acc.y = fmaf(v0.y, e0, acc.y);
        acc.z = fmaf(v0.z, e0, acc.z); acc.w = fmaf(v0.w, e0, acc.w);
    }

    float4 sc = *(reinterpret_cast<const float4*>(scale) + lane);
    float4 sh = *(reinterpret_cast<const float4*>(shift) + lane);
    float4 res;
    res.x = fmaxf(fmaf(acc.x, sc.x, sh.x), 0.f);
    res.y = fmaxf(fmaf(acc.y, sc.y, sh.y), 0.f);
    res.z = fmaxf(fmaf(acc.z, sc.z, sh.z), 0.f);
    res.w = fmaxf(fmaf(acc.w, sc.w, sh.w), 0.f);
    *(reinterpret_cast<float4*>(out + (size_t)node * 128) + lane) = res;
}

// ------------- fused mean-pool + head (block per graph) ------------------
__global__ void pool_head_kernel(const float* __restrict__ h,
                                 const int* __restrict__ batch,
                                 const float* __restrict__ W1,
                                 const float* __restrict__ b1,
                                 const float* __restrict__ W2,
                                 const float* __restrict__ b2,
                                 float* __restrict__ out)
{
    __shared__ float sp[HIDDEN];
    __shared__ float sred[128];
    __shared__ int srange[2];
    const int g = blockIdx.x;
    const int t = threadIdx.x;

    if (t < 2) {
        int key = g + t;
        int lo = 0, hi = N_NODES;
        while (lo < hi) {
            int mid = (lo + hi) >> 1;
            if (__ldg(batch + mid) < key) lo = mid + 1; else hi = mid;
        }
        srange[t] = lo;
    }
    __syncthreads();
    const int start = srange[0];
    const int end   = srange[1];

    float sum = 0.f;
    for (int n = start; n < end; n++)
        sum += h[(size_t)n * HIDDEN + t];
    float inv = 1.0f / fmaxf((float)(end - start), 1.0f);
    sp[t] = sum * inv;
    __syncthreads();

    float val = 0.f;
    if (t < 64) {
        float acc = __ldg(b1 + t);
        #pragma unroll 8
        for (int k = 0; k < HIDDEN; k++)
            acc = fmaf(sp[k], __ldg(W1 + k * 64 + t), acc);
        val = fmaxf(acc, 0.f) * __ldg(W2 + t);
    }
    sred[t] = val;
    __syncthreads();
    for (int s = 64; s > 0; s >>= 1) {
        if (t < s) sred[t] += sred[t + s];
        __syncthreads();
    }
    if (t == 0) out[g] = sred[0] + __ldg(b2);
}

// -------------------------------------------------------------------------
extern "C" void kernel_launch(void* const* d_in, const int* in_sizes, int n_in,
                              void* d_out, int out_size)
{
    (void)in_sizes; (void)n_in; (void)out_size;
    const float* x     = (const float*)d_in[0];
    const int*   ei    = (const int*)  d_in[1];
    const float* ea    = (const float*)d_in[2];
    const int*   batch = (const int*)  d_in[3];
    const float* P[21];
    for (int i = 0; i < 21; i++) P[i] = (const float*)d_in[4 + i];
    const float* head_w1 = (const float*)d_in[25];
    const float* head_b1 = (const float*)d_in[26];
    const float* head_w2 = (const float*)d_in[27];
    const float* head_b2 = (const float*)d_in[28];
    float* out = (float*)d_out;

    float *hr, *ho, *ha, *hb, *scale, *shift;
    uint32_t *Bf, *af1;
    int *deg, *epos, *incl, *bsum, *boff;
    int2* csr;
    cudaGetSymbolAddress((void**)&hr,    g_hr);
    cudaGetSymbolAddress((void**)&ho,    g_ho);
    cudaGetSymbolAddress((void**)&ha,    g_ha);
    cudaGetSymbolAddress((void**)&hb,    g_hb);
    cudaGetSymbolAddress((void**)&scale, g_scale);
    cudaGetSymbolAddress((void**)&shift, g_shift);
    cudaGetSymbolAddress((void**)&Bf,    g_Bf);
    cudaGetSymbolAddress((void**)&af1,   g_af1);
    cudaGetSymbolAddress((void**)&deg,   g_deg);
    cudaGetSymbolAddress((void**)&epos,  g_epos);
    cudaGetSymbolAddress((void**)&incl,  g_incl);
    cudaGetSymbolAddress((void**)&bsum,  g_bsum);
    cudaGetSymbolAddress((void**)&boff,  g_boff);
    cudaGetSymbolAddress((void**)&csr,   g_csr);

    const int* src = ei;
    const int* dst = ei + N_EDGES;

    const int gather_blocks = (N_NODES * 32 + 255) / 256;

    cudaMemsetAsync(deg, 0, N_NODES * sizeof(int), 0);
    hist_kernel<<<(N_EDGES + 255) / 256, 256>>>(dst, deg, epos);
    scan1_kernel<<<N_SCAN_BLOCKS, SCAN_BLK>>>(deg, incl, bsum);
    scan2_kernel<<<1, 512>>>(bsum, boff);
    fill_kernel<<<(N_EDGES + 255) / 256, 256>>>(src, dst, ea, deg, incl, boff,
                                                epos, csr);
    gather64_kernel<<<gather_blocks, 256>>>(x, deg, incl, boff, csr, ho);
    prep_all_kernel<<<321, 256>>>(P[0], P[2], P[7], P[9], P[14], P[16],
                                  P[1], P[3], P[4], P[5], P[6],
                                  P[8], P[10], P[11], P[12], P[13],
                                  P[15], P[17], P[18], P[19], P[20]);

    // ---- Layer 0: [agg0|x] @ [Wr0;Wo0] + BN + ReLU -> A-fragments (af1)
    gemm_fused_kernel<<<N_TILES64, 128>>>(
        ho, x, Bf, scale + 0 * HIDDEN, shift + 0 * HIDDEN, af1);

    // ---- Layer 1: M=128 frag GEMM -> hr,ho ; warp-per-node gather -> hb
    gemm_frag_kernel<<<N_TILES128, 512>>>(af1, Bf + 16384, hr, ho);
    gather_fused_kernel<<<gather_blocks, 256>>>(hr, ho, deg, incl, boff, csr,
                                                scale + 1 * HIDDEN, shift + 1 * HIDDEN, hb);

    // ---- Layer 2: M=128 direct GEMM -> hr,ho ; gather -> ha
    gemm_direct_kernel<<<N_TILES128, 512>>>(hb, Bf + 49152, hr, ho);
    gather_fused_kernel<<<gather_blocks, 256>>>(hr, ho, deg, incl, boff, csr,
                                                scale + 2 * HIDDEN, shift + 2 * HIDDEN, ha);

    // ---- Fused mean pool + head ----
    pool_head_kernel<<<N_GRAPHS, 128>>>(ha, batch, head_w1, head_b1,
                                        head_w2, head_b2, out);
}

// round 17
// speedup vs baseline: 1.0740x; 1.0740x over previous
#include <cuda_runtime.h>
#include <cstdint>
#include <cstddef>

#define N_NODES 100000
#define N_EDGES 1600000
#define F_IN    64
#define HIDDEN  128
#define N_GRAPHS 1024
#define EPS 1e-5f

#define SCAN_BLK 256
#define N_SCAN_BLOCKS ((N_NODES + SCAN_BLK - 1) / SCAN_BLK)   // 391
#define N_TILES64 ((N_NODES + 63) / 64)                        // 1563
#define HIST_BLOCKS ((N_EDGES + 255) / 256)                    // 6250

// ---------------- static scratch (no allocation allowed) ----------------
__device__ float g_hr[(size_t)N_NODES * HIDDEN];
__device__ float g_ho[(size_t)N_NODES * HIDDEN];    // also agg0
__device__ float g_ha[(size_t)N_NODES * HIDDEN];    // final activations
__device__ float g_hb[(size_t)N_NODES * HIDDEN];    // layer-1 output (row-major)

// A-fragment image for layer-1 GEMM (split bf16, quad-major, 8192 words/tile)
__device__ __align__(16) uint32_t g_af1[(size_t)N_TILES64 * 8192];

__device__ float g_scale[3][HIDDEN];
__device__ float g_shift[3][HIDDEN];

// B fragments (split bf16, quad-major):
// layer0 (fused, N=128,K'=128): 16384 words @0 ; layers1/2 (N=256,K=128): 32768 @16384/49152
__device__ __align__(16) uint32_t g_Bf[16384 + 32768 + 32768];

__device__ int   g_deg[N_NODES];
__device__ int   g_epos[N_EDGES];
__device__ int   g_incl[N_SCAN_BLOCKS * SCAN_BLK];
__device__ int   g_bsum[N_SCAN_BLOCKS];
__device__ int   g_boff[N_SCAN_BLOCKS];
__device__ __align__(8) int2 g_csr[N_EDGES];        // (src, ew-bits)

__device__ __forceinline__ uint32_t bf16x2(float x0, float x1) {
    uint32_t r;
    asm("cvt.rn.bf16x2.f32 %0, %1, %2;" : "=r"(r) : "f"(x1), "f"(x0));
    return r;
}
__device__ __forceinline__ void split2(float a, float b, uint32_t& hi, uint32_t& lo) {
    hi = bf16x2(a, b);
    float h0 = __uint_as_float(hi << 16);
    float h1 = __uint_as_float(hi & 0xffff0000u);
    lo = bf16x2(a - h0, b - h1);
}

__device__ __forceinline__ void mma16(float* c, uint4 a, uint32_t b0, uint32_t b1) {
    asm volatile(
        "mma.sync.aligned.m16n8k16.row.col.f32.bf16.bf16.f32 "
        "{%0,%1,%2,%3}, {%4,%5,%6,%7}, {%8,%9}, {%0,%1,%2,%3};"
        : "+f"(c[0]), "+f"(c[1]), "+f"(c[2]), "+f"(c[3])
        : "r"(a.x), "r"(a.y), "r"(a.z), "r"(a.w), "r"(b0), "r"(b1));
}
__device__ __forceinline__ void mma_row(float (*accRow)[4], uint4 a,
                                        uint4 b0, uint4 b1, uint4 b2, uint4 b3) {
    mma16(accRow[0], a, b0.x, b0.y);  mma16(accRow[1], a, b0.z, b0.w);
    mma16(accRow[2], a, b1.x, b1.y);  mma16(accRow[3], a, b1.z, b1.w);
    mma16(accRow[4], a, b2.x, b2.y);  mma16(accRow[5], a, b2.z, b2.w);
    mma16(accRow[6], a, b3.x, b3.y);  mma16(accRow[7], a, b3.z, b3.w);
}

// ========== hist (+epos) fused with weight prep + BN fold ================
// blocks [0, HIST_BLOCKS): edge histogram, record epos
// blocks [HIST_BLOCKS, HIST_BLOCKS+64): layer-0 B image
// blocks [HIST_BLOCKS+64, HIST_BLOCKS+320): layers-1/2 B images
// block  HIST_BLOCKS+320: BN fold
__global__ void hist_prep_kernel(const int* __restrict__ dst,
                                 int* __restrict__ deg,
                                 int* __restrict__ epos,
                                 const float* __restrict__ Wr0, const float* __restrict__ Wo0,
                                 const float* __restrict__ Wr1, const float* __restrict__ Wo1,
                                 const float* __restrict__ Wr2, const float* __restrict__ Wo2,
                                 const float* __restrict__ br0, const float* __restrict__ g0,
                                 const float* __restrict__ b0,  const float* __restrict__ m0,
                                 const float* __restrict__ v0,
                                 const float* __restrict__ br1, const float* __restrict__ g1,
                                 const float* __restrict__ b1,  const float* __restrict__ m1,
                                 const float* __restrict__ v1,
                                 const float* __restrict__ br2, const float* __restrict__ g2,
                                 const float* __restrict__ b2,  const float* __restrict__ m2,
                                 const float* __restrict__ v2)
{
    int blk = blockIdx.x;
    if (blk < HIST_BLOCKS) {
        int e = blk * 256 + threadIdx.x;
        if (e < N_EDGES) epos[e] = atomicAdd(deg + __ldg(dst + e), 1);
        return;
    }
    blk -= HIST_BLOCKS;
    if (blk < 64) {
        int rem = blk * 256 + threadIdx.x;
        int w    = rem & 3;
        int lane = (rem >> 2) & 31;
        int q    = (rem >> 7) & 3;
        int ng   = (rem >> 9) & 1;
        int t    = rem >> 10;
        int ks   = t & 7;
        int hilo = t >> 3;
        int idx  = q * 4 + w;
        int nt = idx >> 1, breg = idx & 1;
        int k0 = ks * 16 + (lane & 3) * 2 + breg * 8;
        int n  = ng * 64 + nt * 8 + (lane >> 2);
        float w0, w1;
        if (k0 < 64) { w0 = __ldg(Wr0 + k0 * 128 + n); w1 = __ldg(Wr0 + (k0 + 1) * 128 + n); }
        else         { w0 = __ldg(Wo0 + (k0 - 64) * 128 + n); w1 = __ldg(Wo0 + (k0 - 63) * 128 + n); }
        uint32_t hi, lo;
        split2(w0, w1, hi, lo);
        g_Bf[rem] = hilo ? lo : hi;
    } else if (blk < 320) {
        int id = (blk - 64) * 256 + threadIdx.x;
        int base, rem;
        const float *Wr, *Wo;
        if (id < 32768) { base = 16384; rem = id;          Wr = Wr1; Wo = Wo1; }
        else            { base = 49152; rem = id - 32768;  Wr = Wr2; Wo = Wo2; }
        int w    = rem & 3;
        int lane = (rem >> 2) & 31;
        int q    = (rem >> 7) & 3;
        int ng   = (rem >> 9) & 3;
        int t    = rem >> 11;
        int ks   = t & 7;
        int hilo = t >> 3;
        int idx  = q * 4 + w;
        int nt = idx >> 1, breg = idx & 1;
        int k0 = ks * 16 + (lane & 3) * 2 + breg * 8;
        int n  = ng * 64 + nt * 8 + (lane >> 2);
        int jj = n & 127;
        const float* W = (n < 128) ? Wr : Wo;
        float w0 = __ldg(W + (k0 + 0) * 128 + jj);
        float w1 = __ldg(W + (k0 + 1) * 128 + jj);
        uint32_t hi, lo;
        split2(w0, w1, hi, lo);
        g_Bf[base + rem] = hilo ? lo : hi;
    } else {
        int j = threadIdx.x;
        if (j < 128) {
            for (int l = 0; l < 3; l++) {
                const float* br = (l == 0) ? br0 : (l == 1) ? br1 : br2;
                const float* g  = (l == 0) ? g0  : (l == 1) ? g1  : g2;
                const float* b  = (l == 0) ? b0  : (l == 1) ? b1  : b2;
                const float* m  = (l == 0) ? m0  : (l == 1) ? m1  : m2;
                const float* v  = (l == 0) ? v0  : (l == 1) ? v1  : v2;
                float s = g[j] * rsqrtf(v[j] + EPS);
                g_scale[l][j] = s;
                g_shift[l][j] = (br[j] - m[j]) * s + b[j];
            }
        }
    }
}

__global__ void scan1_kernel(const int* __restrict__ deg,
                             int* __restrict__ incl, int* __restrict__ bsum)
{
    __shared__ int s[SCAN_BLK];
    int gid = blockIdx.x * SCAN_BLK + threadIdx.x;
    int v = (gid < N_NODES) ? deg[gid] : 0;
    s[threadIdx.x] = v;
    __syncthreads();
    #pragma unroll
    for (int off = 1; off < SCAN_BLK; off <<= 1) {
        int t = (threadIdx.x >= off) ? s[threadIdx.x - off] : 0;
        __syncthreads();
        s[threadIdx.x] += t;
        __syncthreads();
    }
    incl[gid] = s[threadIdx.x];
    if (threadIdx.x == SCAN_BLK - 1) bsum[blockIdx.x] = s[threadIdx.x];
}

__global__ void scan2_kernel(const int* __restrict__ bsum, int* __restrict__ boff)
{
    __shared__ int s[512];
    int t = threadIdx.x;
    s[t] = (t < N_SCAN_BLOCKS) ? bsum[t] : 0;
    __syncthreads();
    #pragma unroll
    for (int off = 1; off < 512; off <<= 1) {
        int v = (t >= off) ? s[t - off] : 0;
        __syncthreads();
        s[t] += v;
        __syncthreads();
    }
    if (t < N_SCAN_BLOCKS) boff[t] = s[t] - bsum[t];
}

__global__ void fill_kernel(const int* __restrict__ src,
                            const int* __restrict__ dst,
                            const float* __restrict__ ew,
                            const int* __restrict__ deg,
                            const int* __restrict__ incl,
                            const int* __restrict__ boff,
                            const int* __restrict__ epos,
                            int2* __restrict__ csr)
{
    int e = blockIdx.x * blockDim.x + threadIdx.x;
    if (e >= N_EDGES) return;
    int d = __ldg(dst + e);
    int base = __ldg(incl + d) - __ldg(deg + d) + __ldg(boff + (d >> 8));
    csr[base + __ldg(epos + e)] =
        make_int2(__ldg(src + e), __float_as_int(__ldg(ew + e)));
}

// ============== layer-0 gather: agg[n] = Σ ew*x[src] (D=64) ==============
__global__ void gather64_kernel(const float* __restrict__ x,
                                const int* __restrict__ deg,
                                const int* __restrict__ incl,
                                const int* __restrict__ boff,
                                const int2* __restrict__ csr,
                                float* __restrict__ agg)
{
    int node = (blockIdx.x * blockDim.x + threadIdx.x) >> 5;
    if (node >= N_NODES) return;
    int lane = threadIdx.x & 31;
    int end = __ldg(incl + node) + __ldg(boff + (node >> 8));
    int beg = end - __ldg(deg + node);

    const float2* x2 = reinterpret_cast<const float2*>(x);
    float2 acc = make_float2(0.f, 0.f);
    int i = beg;
    for (; i + 1 < end; i += 2) {
        int2 p0 = __ldg(csr + i);
        int2 p1 = __ldg(csr + i + 1);
        float e0 = __int_as_float(p0.y);
        float e1 = __int_as_float(p1.y);
        float2 v0 = x2[(size_t)p0.x * 32 + lane];
        float2 v1 = x2[(size_t)p1.x * 32 + lane];
        acc.x = fmaf(v0.x, e0, acc.x); acc.y = fmaf(v0.y, e0, acc.y);
        acc.x = fmaf(v1.x, e1, acc.x); acc.y = fmaf(v1.y, e1, acc.y);
    }
    if (i < end) {
        int2 p0 = __ldg(csr + i);
        float e0 = __int_as_float(p0.y);
        float2 v0 = x2[(size_t)p0.x * 32 + lane];
        acc.x = fmaf(v0.x, e0, acc.x); acc.y = fmaf(v0.y, e0, acc.y);
    }
    reinterpret_cast<float2*>(agg + (size_t)node * 64)[lane] = acc;
}

// ====== layer-0 fused GEMM (smem-staged, R13-proven) -> af1 fragments ====
__global__ void __launch_bounds__(128, 4)
gemm_fused_kernel(const float* __restrict__ agg, const float* __restrict__ h,
                  const uint32_t* __restrict__ Bf,
                  const float* __restrict__ scale, const float* __restrict__ shift,
                  uint32_t* __restrict__ AFrag)
{
    extern __shared__ float smem[];
    float*    sRaw  = smem;                                   // 64*68 floats
    uint32_t* fragU = reinterpret_cast<uint32_t*>(smem + 64 * 68);  // 4096 words

    const int tid  = threadIdx.x;
    const int w    = tid >> 5;
    const int lane = tid & 31;
    const int mg   = w >> 1;
    const int ng   = w & 1;
    const int n0   = blockIdx.x * 64;

    float acc[2][8][4];
    #pragma unroll
    for (int mt = 0; mt < 2; mt++)
        #pragma unroll
        for (int nt = 0; nt < 8; nt++)
            #pragma unroll
            for (int r = 0; r < 4; r++) acc[mt][nt][r] = 0.f;

    const uint4* fragQ = reinterpret_cast<const uint4*>(fragU);
    const uint4* BfQ   = reinterpret_cast<const uint4*>(Bf);

    for (int c = 0; c < 2; c++) {
        const float* srcP = (c == 0) ? agg : h;

        for (int i = tid; i < 1024; i += 128) {
            int row = i >> 4, cc = i & 15;
            uint4 v = make_uint4(0u, 0u, 0u, 0u);
            if (n0 + row < N_NODES)
                v = *reinterpret_cast<const uint4*>(srcP + (size_t)(n0 + row) * 64 + cc * 4);
            *reinterpret_cast<uint4*>(&sRaw[row * 68 + cc * 4]) = v;
        }
        __syncthreads();

        #pragma unroll
        for (int j = 0; j < 2; j++) {
            int ksl = (w & 1) + 2 * j;
            int cbase = (mg * 4 + ksl) * 4;
            #pragma unroll
            for (int mt = 0; mt < 2; mt++) {
                uint32_t hwv[4], lwv[4];
                #pragma unroll
                for (int r = 0; r < 4; r++) {
                    int row = mg * 32 + mt * 16 + (lane >> 2) + (r & 1) * 8;
                    int k0  = ksl * 16 + (lane & 3) * 2 + ((r >> 1) & 1) * 8;
                    split2(sRaw[row * 68 + k0], sRaw[row * 68 + k0 + 1], hwv[r], lwv[r]);
                }
                *reinterpret_cast<uint4*>(&fragU[((cbase + mt * 2 + 0) * 32 + lane) * 4]) =
                    make_uint4(hwv[0], hwv[1], hwv[2], hwv[3]);
                *reinterpret_cast<uint4*>(&fragU[((cbase + mt * 2 + 1) * 32 + lane) * 4]) =
                    make_uint4(lwv[0], lwv[1], lwv[2], lwv[3]);
            }
        }
        __syncthreads();

        for (int ksl = 0; ksl < 4; ksl++) {
            int gks = c * 4 + ksl;
            const uint4* aB = fragQ + ((mg * 4 + ksl) * 4) * 32 + lane;
            uint4 a0h = aB[0 * 32];
            uint4 a0l = aB[1 * 32];
            uint4 a1h = aB[2 * 32];
            uint4 a1l = aB[3 * 32];

            const uint4* bHi = BfQ + (((0 * 8 + gks) * 2 + ng) * 4) * 32 + lane;
            uint4 bh0 = __ldg(bHi + 0 * 32);
            uint4 bh1 = __ldg(bHi + 1 * 32);
            uint4 bh2 = __ldg(bHi + 2 * 32);
            uint4 bh3 = __ldg(bHi + 3 * 32);

            mma_row(acc[0], a0h, bh0, bh1, bh2, bh3);
            mma_row(acc[1], a1h, bh0, bh1, bh2, bh3);
            mma_row(acc[0], a0l, bh0, bh1, bh2, bh3);
            mma_row(acc[1], a1l, bh0, bh1, bh2, bh3);

            const uint4* bLo = BfQ + (((1 * 8 + gks) * 2 + ng) * 4) * 32 + lane;
            uint4 bl0 = __ldg(bLo + 0 * 32);
            uint4 bl1 = __ldg(bLo + 1 * 32);
            uint4 bl2 = __ldg(bLo + 2 * 32);
            uint4 bl3 = __ldg(bLo + 3 * 32);

            mma_row(acc[0], a0h, bl0, bl1, bl2, bl3);
            mma_row(acc[1], a1h, bl0, bl1, bl2, bl3);
        }
        __syncthreads();
    }

    // ---- epilogue: BN + bias + ReLU, emit A-fragments for layer 1 ----
    uint32_t* AF = AFrag + (size_t)blockIdx.x * 8192;
    #pragma unroll
    for (int mt = 0; mt < 2; mt++) {
        #pragma unroll
        for (int q = 0; q < 4; q++) {
            int ks = ng * 4 + q;
            int c0 = ng * 64 + 2 * q * 8 + 2 * (lane & 3);
            float2 sc0 = *reinterpret_cast<const float2*>(scale + c0);
            float2 sh0 = *reinterpret_cast<const float2*>(shift + c0);
            float2 sc1 = *reinterpret_cast<const float2*>(scale + c0 + 8);
            float2 sh1 = *reinterpret_cast<const float2*>(shift + c0 + 8);
            float v00 = fmaxf(fmaf(acc[mt][2*q][0],   sc0.x, sh0.x), 0.f);
            float v01 = fmaxf(fmaf(acc[mt][2*q][1],   sc0.y, sh0.y), 0.f);
            float v10 = fmaxf(fmaf(acc[mt][2*q][2],   sc0.x, sh0.x), 0.f);
            float v11 = fmaxf(fmaf(acc[mt][2*q][3],   sc0.y, sh0.y), 0.f);
            float w00 = fmaxf(fmaf(acc[mt][2*q+1][0], sc1.x, sh1.x), 0.f);
            float w01 = fmaxf(fmaf(acc[mt][2*q+1][1], sc1.y, sh1.y), 0.f);
            float w10 = fmaxf(fmaf(acc[mt][2*q+1][2], sc1.x, sh1.x), 0.f);
            float w11 = fmaxf(fmaf(acc[mt][2*q+1][3], sc1.y, sh1.y), 0.f);
            uint4 hi, lo;
            split2(v00, v01, hi.x, lo.x);
            split2(v10, v11, hi.y, lo.y);
            split2(w00, w01, hi.z, lo.z);
            split2(w10, w11, hi.w, lo.w);
            int qb = (mg * 8 + ks) * 4;
            *reinterpret_cast<uint4*>(&AF[((qb + mt * 2 + 0) * 32 + lane) * 4]) = hi;
            *reinterpret_cast<uint4*>(&AF[((qb + mt * 2 + 1) * 32 + lane) * 4]) = lo;
        }
    }
}
#define GEMM_FUSED_SMEM (64 * 68 * 4 + 4096 * 4)

// ====== layer-1 GEMM from gmem A-fragments (no smem, no convert) =========
__global__ void __launch_bounds__(256, 2)
gemm_frag_kernel(const uint32_t* __restrict__ AFrag,
                 const uint32_t* __restrict__ Bf,
                 float* __restrict__ hr,
                 float* __restrict__ ho)
{
    const int w    = threadIdx.x >> 5;
    const int lane = threadIdx.x & 31;
    const int mg   = w >> 2;
    const int ng   = w & 3;
    const int n0   = blockIdx.x * 64;

    float acc[2][8][4];
    #pragma unroll
    for (int mt = 0; mt < 2; mt++)
        #pragma unroll
        for (int nt = 0; nt < 8; nt++)
            #pragma unroll
            for (int r = 0; r < 4; r++) acc[mt][nt][r] = 0.f;

    const uint4* AQ  = reinterpret_cast<const uint4*>(AFrag) + (size_t)blockIdx.x * 2048;
    const uint4* BfQ = reinterpret_cast<const uint4*>(Bf);

    for (int ks = 0; ks < 8; ks++) {
        const uint4* aB = AQ + ((mg * 8 + ks) * 4) * 32 + lane;
        uint4 a0h = __ldg(aB + 0 * 32);
        uint4 a0l = __ldg(aB + 1 * 32);
        uint4 a1h = __ldg(aB + 2 * 32);
        uint4 a1l = __ldg(aB + 3 * 32);

        const uint4* bHi = BfQ + (((0 * 8 + ks) * 4 + ng) * 4) * 32 + lane;
        uint4 bh0 = __ldg(bHi + 0 * 32);
        uint4 bh1 = __ldg(bHi + 1 * 32);
        uint4 bh2 = __ldg(bHi + 2 * 32);
        uint4 bh3 = __ldg(bHi + 3 * 32);

        mma_row(acc[0], a0h, bh0, bh1, bh2, bh3);
        mma_row(acc[1], a1h, bh0, bh1, bh2, bh3);
        mma_row(acc[0], a0l, bh0, bh1, bh2, bh3);
        mma_row(acc[1], a1l, bh0, bh1, bh2, bh3);

        const uint4* bLo = BfQ + (((1 * 8 + ks) * 4 + ng) * 4) * 32 + lane;
        uint4 bl0 = __ldg(bLo + 0 * 32);
        uint4 bl1 = __ldg(bLo + 1 * 32);
        uint4 bl2 = __ldg(bLo + 2 * 32);
        uint4 bl3 = __ldg(bLo + 3 * 32);

        mma_row(acc[0], a0h, bl0, bl1, bl2, bl3);
        mma_row(acc[1], a1h, bl0, bl1, bl2, bl3);
    }

    float* dst = (ng < 2) ? hr : ho;
    const int colbase = (ng & 1) * 64;
    #pragma unroll
    for (int mt = 0; mt < 2; mt++) {
        int row = n0 + mg * 32 + mt * 16 + (lane >> 2);
        #pragma unroll
        for (int nt = 0; nt < 8; nt++) {
            int col = colbase + nt * 8 + 2 * (lane & 3);
            if (row < N_NODES)
                *reinterpret_cast<float2*>(dst + (size_t)row * 128 + col) =
                    make_float2(acc[mt][nt][0], acc[mt][nt][1]);
            if (row + 8 < N_NODES)
                *reinterpret_cast<float2*>(dst + (size_t)(row + 8) * 128 + col) =
                    make_float2(acc[mt][nt][2], acc[mt][nt][3]);
        }
    }
}

// ====== layer-2 GEMM (row-major input, smem stage+convert; R13-proven) ===
template <int KS16>
__global__ void __launch_bounds__(256, 2)
gemm_mma_kernel(const float* __restrict__ h,
                const uint32_t* __restrict__ Bf,
                float* __restrict__ hr,
                float* __restrict__ ho)
{
    constexpr int K = KS16 * 16;
    extern __shared__ float smem[];
    float*    sRaw  = smem;
    uint32_t* fragU = reinterpret_cast<uint32_t*>(smem + 64 * (K + 4));

    const int tid  = threadIdx.x;
    const int w    = tid >> 5;
    const int lane = tid & 31;
    const int mg   = w >> 2;
    const int ng   = w & 3;
    const int n0   = blockIdx.x * 64;

    for (int i = tid; i < 16 * K; i += 256) {
        int row = i / (K / 4);
        int c   = i % (K / 4);
        uint4 v = make_uint4(0u, 0u, 0u, 0u);
        if (n0 + row < N_NODES)
            v = *reinterpret_cast<const uint4*>(h + (size_t)(n0 + row) * K + c * 4);
        *reinterpret_cast<uint4*>(&sRaw[row * (K + 4) + c * 4]) = v;
    }
    __syncthreads();

    for (int j = 0; j < KS16 / 4; j++) {
        int ks = ng + 4 * j;
        int cbase = (mg * KS16 + ks) * 4;
        #pragma unroll
        for (int mt = 0; mt < 2; mt++) {
            uint32_t hwv[4], lwv[4];
            #pragma unroll
            for (int r = 0; r < 4; r++) {
                int row = mg * 32 + mt * 16 + (lane >> 2) + (r & 1) * 8;
                int k0  = ks * 16 + (lane & 3) * 2 + ((r >> 1) & 1) * 8;
                split2(sRaw[row * (K + 4) + k0], sRaw[row * (K + 4) + k0 + 1],
                       hwv[r], lwv[r]);
            }
            *reinterpret_cast<uint4*>(&fragU[((cbase + mt * 2 + 0) * 32 + lane) * 4]) =
                make_uint4(hwv[0], hwv[1], hwv[2], hwv[3]);
            *reinterpret_cast<uint4*>(&fragU[((cbase + mt * 2 + 1) * 32 + lane) * 4]) =
                make_uint4(lwv[0], lwv[1], lwv[2], lwv[3]);
        }
    }
    __syncthreads();

    float acc[2][8][4];
    #pragma unroll
    for (int mt = 0; mt < 2; mt++)
        #pragma unroll
        for (int nt = 0; nt < 8; nt++)
            #pragma unroll
            for (int r = 0; r < 4; r++) acc[mt][nt][r] = 0.f;

    const uint4* fragQ = reinterpret_cast<const uint4*>(fragU);
    const uint4* BfQ   = reinterpret_cast<const uint4*>(Bf);

    for (int ks = 0; ks < KS16; ks++) {
        const uint4* aB = fragQ + ((mg * KS16 + ks) * 4) * 32 + lane;
        uint4 a0h = aB[0 * 32];
        uint4 a0l = aB[1 * 32];
        uint4 a1h = aB[2 * 32];
        uint4 a1l = aB[3 * 32];

        const uint4* bHi = BfQ + (((0 * KS16 + ks) * 4 + ng) * 4) * 32 + lane;
        uint4 bh0 = __ldg(bHi + 0 * 32);
        uint4 bh1 = __ldg(bHi + 1 * 32);
        uint4 bh2 = __ldg(bHi + 2 * 32);
        uint4 bh3 = __ldg(bHi + 3 * 32);

        mma_row(acc[0], a0h, bh0, bh1, bh2, bh3);
        mma_row(acc[1], a1h, bh0, bh1, bh2, bh3);
        mma_row(acc[0], a0l, bh0, bh1, bh2, bh3);
        mma_row(acc[1], a1l, bh0, bh1, bh2, bh3);

        const uint4* bLo = BfQ + (((1 * KS16 + ks) * 4 + ng) * 4) * 32 + lane;
        uint4 bl0 = __ldg(bLo + 0 * 32);
        uint4 bl1 = __ldg(bLo + 1 * 32);
        uint4 bl2 = __ldg(bLo + 2 * 32);
        uint4 bl3 = __ldg(bLo + 3 * 32);

        mma_row(acc[0], a0h, bl0, bl1, bl2, bl3);
        mma_row(acc[1], a1h, bl0, bl1, bl2, bl3);
    }

    float* dst = (ng < 2) ? hr : ho;
    const int colbase = (ng & 1) * 64;
    #pragma unroll
    for (int mt = 0; mt < 2; mt++) {
        int row = n0 + mg * 32 + mt * 16 + (lane >> 2);
        #pragma unroll
        for (int nt = 0; nt < 8; nt++) {
            int col = colbase + nt * 8 + 2 * (lane & 3);
            if (row < N_NODES)
                *reinterpret_cast<float2*>(dst + (size_t)row * 128 + col) =
                    make_float2(acc[mt][nt][0], acc[mt][nt][1]);
            if (row + 8 < N_NODES)
                *reinterpret_cast<float2*>(dst + (size_t)(row + 8) * 128 + col) =
                    make_float2(acc[mt][nt][2], acc[mt][nt][3]);
        }
    }
}
#define GEMM_SMEM(K) (64 * ((K) + 4) * 4 + (K) * 256)

// === fused gather + root + BN + ReLU (warp-per-node, row-major out) ======
__global__ void gather_fused_kernel(const float* __restrict__ hr,
                                    const float* __restrict__ ho,
                                    const int* __restrict__ deg,
                                    const int* __restrict__ incl,
                                    const int* __restrict__ boff,
                                    const int2* __restrict__ csr,
                                    const float* __restrict__ scale,
                                    const float* __restrict__ shift,
                                    float* __restrict__ out)
{
    int node = (blockIdx.x * blockDim.x + threadIdx.x) >> 5;
    if (node >= N_NODES) return;
    int lane = threadIdx.x & 31;
    int end = __ldg(incl + node) + __ldg(boff + (node >> 8));
    int beg = end - __ldg(deg + node);

    const float4* hr4 = reinterpret_cast<const float4*>(hr);
    float4 acc = *(reinterpret_cast<const float4*>(ho + (size_t)node * 128) + lane);

    int i = beg;
    for (; i + 3 < end; i += 4) {
        int2 p0 = __ldg(csr + i);
        int2 p1 = __ldg(csr + i + 1);
        int2 p2 = __ldg(csr + i + 2);
        int2 p3 = __ldg(csr + i + 3);
        float4 v0 = hr4[(size_t)p0.x * 32 + lane];
        float4 v1 = hr4[(size_t)p1.x * 32 + lane];
        float4 v2 = hr4[(size_t)p2.x * 32 + lane];
        float4 v3 = hr4[(size_t)p3.x * 32 + lane];
        float e0 = __int_as_float(p0.y), e1 = __int_as_float(p1.y);
        float e2 = __int_as_float(p2.y), e3 = __int_as_float(p3.y);
        acc.x = fmaf(v0.x, e0, acc.x); acc.y = fmaf(v0.y, e0, acc.y);
        acc.z = fmaf(v0.z, e0, acc.z); acc.w = fmaf(v0.w, e0, acc.w);
        acc.x = fmaf(v1.x, e1, acc.x); acc.y = fmaf(v1.y, e1, acc.y);
        acc.z = fmaf(v1.z, e1, acc.z); acc.w = fmaf(v1.w, e1, acc.w);
        acc.x = fmaf(v2.x, e2, acc.x); acc.y = fmaf(v2.y, e2, acc.y);
        acc.z = fmaf(v2.z, e2, acc.z); acc.w = fmaf(v2.w, e2, acc.w);
        acc.x = fmaf(v3.x, e3, acc.x); acc.y = fmaf(v3.y, e3, acc.y);
        acc.z = fmaf(v3.z, e3, acc.z); acc.w = fmaf(v3.w, e3, acc.w);
    }
    for (; i < end; i++) {
        int2 p0 = __ldg(csr + i);
        float e0 = __int_as_float(p0.y);
        float4 v0 = hr4[(size_t)p0.x * 32 + lane];
        acc.x = fmaf(v0.x, e0, acc.x); acc.y = fmaf(v0.y, e0, acc.y);
        acc.z = fmaf(v0.z, e0, acc.z); acc.w = fmaf(v0.w, e0, acc.w);
    }

    float4 sc = *(reinterpret_cast<const float4*>(scale) + lane);
    float4 sh = *(reinterpret_cast<const float4*>(shift) + lane);
    float4 res;
    res.x = fmaxf(fmaf(acc.x, sc.x, sh.x), 0.f);
    res.y = fmaxf(fmaf(acc.y, sc.y, sh.y), 0.f);
    res.z = fmaxf(fmaf(acc.z, sc.z, sh.z), 0.f);
    res.w = fmaxf(fmaf(acc.w, sc.w, sh.w), 0.f);
    *(reinterpret_cast<float4*>(out + (size_t)node * 128) + lane) = res;
}

// ------------- fused mean-pool + head (block per graph) ------------------
__global__ void pool_head_kernel(const float* __restrict__ h,
                                 const int* __restrict__ batch,
                                 const float* __restrict__ W1,
                                 const float* __restrict__ b1,
                                 const float* __restrict__ W2,
                                 const float* __restrict__ b2,
                                 float* __restrict__ out)
{
    __shared__ float sp[HIDDEN];
    __shared__ float sred[128];
    __shared__ int srange[2];
    const int g = blockIdx.x;
    const int t = threadIdx.x;

    if (t < 2) {
        int key = g + t;
        int lo = 0, hi = N_NODES;
        while (lo < hi) {
            int mid = (lo + hi) >> 1;
            if (__ldg(batch + mid) < key) lo = mid + 1; else hi = mid;
        }
        srange[t] = lo;
    }
    __syncthreads();
    const int start = srange[0];
    const int end   = srange[1];

    float sum = 0.f;
    for (int n = start; n < end; n++)
        sum += h[(size_t)n * HIDDEN + t];
    float inv = 1.0f / fmaxf((float)(end - start), 1.0f);
    sp[t] = sum * inv;
    __syncthreads();

    float val = 0.f;
    if (t < 64) {
        float acc = __ldg(b1 + t);
        #pragma unroll 8
        for (int k = 0; k < HIDDEN; k++)
            acc = fmaf(sp[k], __ldg(W1 + k * 64 + t), acc);
        val = fmaxf(acc, 0.f) * __ldg(W2 + t);
    }
    sred[t] = val;
    __syncthreads();
    for (int s = 64; s > 0; s >>= 1) {
        if (t < s) sred[t] += sred[t + s];
        __syncthreads();
    }
    if (t == 0) out[g] = sred[0] + __ldg(b2);
}

// -------------------------------------------------------------------------
extern "C" void kernel_launch(void* const* d_in, const int* in_sizes, int n_in,
                              void* d_out, int out_size)
{
    (void)in_sizes; (void)n_in; (void)out_size;
    const float* x     = (const float*)d_in[0];
    const int*   ei    = (const int*)  d_in[1];
    const float* ea    = (const float*)d_in[2];
    const int*   batch = (const int*)  d_in[3];
    const float* P[21];
    for (int i = 0; i < 21; i++) P[i] = (const float*)d_in[4 + i];
    const float* head_w1 = (const float*)d_in[25];
    const float* head_b1 = (const float*)d_in[26];
    const float* head_w2 = (const float*)d_in[27];
    const float* head_b2 = (const float*)d_in[28];
    float* out = (float*)d_out;

    float *hr, *ho, *ha, *hb, *scale, *shift;
    uint32_t *Bf, *af1;
    int *deg, *epos, *incl, *bsum, *boff;
    int2* csr;
    cudaGetSymbolAddress((void**)&hr,    g_hr);
    cudaGetSymbolAddress((void**)&ho,    g_ho);
    cudaGetSymbolAddress((void**)&ha,    g_ha);
    cudaGetSymbolAddress((void**)&hb,    g_hb);
    cudaGetSymbolAddress((void**)&scale, g_scale);
    cudaGetSymbolAddress((void**)&shift, g_shift);
    cudaGetSymbolAddress((void**)&Bf,    g_Bf);
    cudaGetSymbolAddress((void**)&af1,   g_af1);
    cudaGetSymbolAddress((void**)&deg,   g_deg);
    cudaGetSymbolAddress((void**)&epos,  g_epos);
    cudaGetSymbolAddress((void**)&incl,  g_incl);
    cudaGetSymbolAddress((void**)&bsum,  g_bsum);
    cudaGetSymbolAddress((void**)&boff,  g_boff);
    cudaGetSymbolAddress((void**)&csr,   g_csr);

    cudaFuncSetAttribute(gemm_fused_kernel,
                         cudaFuncAttributeMaxDynamicSharedMemorySize, GEMM_FUSED_SMEM);
    cudaFuncSetAttribute(gemm_mma_kernel<8>,
                         cudaFuncAttributeMaxDynamicSharedMemorySize, GEMM_SMEM(128));

    const int* src = ei;
    const int* dst = ei + N_EDGES;

    const int gather_blocks = (N_NODES * 32 + 255) / 256;

    cudaMemsetAsync(deg, 0, N_NODES * sizeof(int), 0);
    hist_prep_kernel<<<HIST_BLOCKS + 321, 256>>>(dst, deg, epos,
                                  P[0], P[2], P[7], P[9], P[14], P[16],
                                  P[1], P[3], P[4], P[5], P[6],
                                  P[8], P[10], P[11], P[12], P[13],
                                  P[15], P[17], P[18], P[19], P[20]);
    scan1_kernel<<<N_SCAN_BLOCKS, SCAN_BLK>>>(deg, incl, bsum);
    scan2_kernel<<<1, 512>>>(bsum, boff);
    fill_kernel<<<(N_EDGES + 255) / 256, 256>>>(src, dst, ea, deg, incl, boff,
                                                epos, csr);
    gather64_kernel<<<gather_blocks, 256>>>(x, deg, incl, boff, csr, ho);

    // ---- Layer 0: [agg0|x] @ [Wr0;Wo0] + BN + ReLU -> A-fragments (af1)
    gemm_fused_kernel<<<N_TILES64, 128, GEMM_FUSED_SMEM>>>(
        ho, x, Bf, scale + 0 * HIDDEN, shift + 0 * HIDDEN, af1);

    // ---- Layer 1: frag GEMM -> hr,ho ; warp-per-node gather -> hb
    gemm_frag_kernel<<<N_TILES64, 256>>>(af1, Bf + 16384, hr, ho);
    gather_fused_kernel<<<gather_blocks, 256>>>(hr, ho, deg, incl, boff, csr,
                                                scale + 1 * HIDDEN, shift + 1 * HIDDEN, hb);

    // ---- Layer 2: row-major GEMM -> hr,ho ; gather -> ha
    gemm_mma_kernel<8><<<N_TILES64, 256, GEMM_SMEM(128)>>>(hb, Bf + 49152, hr, ho);
    gather_fused_kernel<<<gather_blocks, 256>>>(hr, ho, deg, incl, boff, csr,
                                                scale + 2 * HIDDEN, shift + 2 * HIDDEN, ha);

    // ---- Fused mean pool + head ----
    pool_head_kernel<<<N_GRAPHS, 128>>>(ha, batch, head_w1, head_b1,
                                        head_w2, head_b2, out);
}